// round 8
// baseline (speedup 1.0000x reference)
// R6 resubmit — R5 kernel unchanged; R6 bench failed on infra (container failed twice), no kernel signal.
#include <cuda_runtime.h>
#include <cuda_fp16.h>
#include <math.h>

#define N_NODES 50000
#define DIM     128
#define N_EDGES 800000
#define NEG_SLOPE 0.2f
#define RPB 16          // rows per GEMM block: 50000/16 = 3125 exact
#define TPAD 20         // padded transposed-smem row stride (floats)

// ---------------- scratch (device globals) ------------------------------------
__device__ __half g_hp16[N_NODES * DIM];  // GAT-parent transformed features (fp16)
__device__ __half g_hc16[N_NODES * DIM];  // GAT-child transformed features (fp16)
__device__ __half g_x16[N_NODES * DIM];   // fp16 copy of x for SAGE gather
__device__ float g_accp[N_NODES * DIM];   // normalized GAT-parent aggregate
__device__ float g_accc[N_NODES * DIM];   // normalized GAT-child aggregate
__device__ float g_accs[N_NODES * DIM];   // SAGE mean(x)
__device__ float g_asp[N_NODES], g_adp[N_NODES];
__device__ float g_asc[N_NODES], g_adc[N_NODES];
__device__ int g_cnt3[3][N_NODES];        // zero-initialized; re-zeroed by k_scan each run
__device__ int g_rp3[3][N_NODES + 1];
__device__ int g_cur3[3][N_NODES];
__device__ int g_csrP[N_EDGES], g_csrC[N_EDGES], g_csrS[N_EDGES];

// ---------------- helpers -----------------------------------------------------
__device__ __forceinline__ float lrelu(float v) { return v > 0.f ? v : NEG_SLOPE * v; }

__device__ __forceinline__ unsigned long long pack2(float lo, float hi) {
    unsigned long long r;
    asm("mov.b64 %0, {%1, %2};" : "=l"(r) : "f"(lo), "f"(hi));
    return r;
}
__device__ __forceinline__ void fma2(unsigned long long& d, unsigned long long a, unsigned long long b) {
    asm("fma.rn.f32x2 %0, %1, %2, %0;" : "+l"(d) : "l"(a), "l"(b));
}
__device__ __forceinline__ float2 unpack2(unsigned long long v) {
    float lo, hi;
    asm("mov.b64 {%0, %1}, %2;" : "=f"(lo), "=f"(hi) : "l"(v));
    return make_float2(lo, hi);
}
__device__ __forceinline__ float4 h2f4(uint2 v) {
    __half2 a = *reinterpret_cast<__half2*>(&v.x);
    __half2 b = *reinterpret_cast<__half2*>(&v.y);
    float2 fa = __half22float2(a), fb = __half22float2(b);
    return make_float4(fa.x, fa.y, fb.x, fb.y);
}

// ---------------- CSR build ---------------------------------------------------
__global__ void __launch_bounds__(256) k_count(
    const int* __restrict__ dP, const int* __restrict__ dC, const int* __restrict__ dS)
{
    int g = blockIdx.y;
    int e = blockIdx.x * 256 + threadIdx.x;
    const int* d = (g == 0) ? dP : (g == 1) ? dC : dS;
    atomicAdd(&g_cnt3[g][d[e]], 1);
}

__global__ void __launch_bounds__(1024) k_scan() {
    int g = blockIdx.x;
    int* cnt = g_cnt3[g];
    int* rp  = g_rp3[g];
    int* cur = g_cur3[g];
    const int CH = 49;  // 1024*49 = 50176 >= 50000
    int t = threadIdx.x, lane = t & 31, w = t >> 5;
    int base = t * CH;
    int s = 0;
    for (int i = 0; i < CH; i++) {
        int idx = base + i;
        if (idx < N_NODES) s += cnt[idx];
    }
    // block exclusive scan of per-thread sums
    __shared__ int wsum[32];
    int v = s;
#pragma unroll
    for (int o = 1; o < 32; o <<= 1) {
        int u = __shfl_up_sync(0xffffffffu, v, o);
        if (lane >= o) v += u;
    }
    if (lane == 31) wsum[w] = v;
    __syncthreads();
    if (w == 0) {
        int z = wsum[lane];
#pragma unroll
        for (int o = 1; o < 32; o <<= 1) {
            int u = __shfl_up_sync(0xffffffffu, z, o);
            if (lane >= o) z += u;
        }
        wsum[lane] = z;
    }
    __syncthreads();
    int off = v - s + (w ? wsum[w - 1] : 0);
    int run = off;
    for (int i = 0; i < CH; i++) {
        int idx = base + i;
        if (idx < N_NODES) {
            rp[idx] = run; cur[idx] = run;
            run += cnt[idx];
            cnt[idx] = 0;   // restore for next graph replay (counts consumed above)
        }
    }
    if (t == 0) rp[N_NODES] = N_EDGES;
}

__global__ void __launch_bounds__(256) k_fill(
    const int* __restrict__ sP, const int* __restrict__ dP,
    const int* __restrict__ sC, const int* __restrict__ dC,
    const int* __restrict__ sS, const int* __restrict__ dS)
{
    int g = blockIdx.y;
    int e = blockIdx.x * 256 + threadIdx.x;
    const int* src = (g == 0) ? sP : (g == 1) ? sC : sS;
    const int* dst = (g == 0) ? dP : (g == 1) ? dC : dS;
    int* csr       = (g == 0) ? g_csrP : (g == 1) ? g_csrC : g_csrS;
    int pos = atomicAdd(&g_cur3[g][dst[e]], 1);
    csr[pos] = src[e];
}

// ---------------- K_feat: h_p = x Wp, h_c = x Wc (f32x2), + alpha dots --------
__global__ void __launch_bounds__(128) k_feat(
    const float* __restrict__ x,
    const float* __restrict__ Wp, const float* __restrict__ Wc,
    const float* __restrict__ apS, const float* __restrict__ apD,
    const float* __restrict__ acS, const float* __restrict__ acD)
{
    __shared__ __align__(16) float sxT[DIM][TPAD];   // transposed x tile
    __shared__ float spart[4][RPB * 4];
    const int j  = threadIdx.x;
    const int r0 = blockIdx.x * RPB;

    for (int t = j; t < RPB * DIM; t += 128) {
        int r = t >> 7, c = t & 127;
        float v = x[r0 * DIM + t];
        sxT[c][r] = v;
        g_x16[r0 * DIM + t] = __float2half_rn(v);   // fp16 copy for SAGE gather
    }
    __syncthreads();

    unsigned long long aP2[8], aC2[8];
#pragma unroll
    for (int p = 0; p < 8; p++) { aP2[p] = 0ull; aC2[p] = 0ull; }

#pragma unroll 4
    for (int k = 0; k < DIM; k++) {
        float wp = Wp[k * DIM + j];
        float wc = Wc[k * DIM + j];
        unsigned long long wp2 = pack2(wp, wp);
        unsigned long long wc2 = pack2(wc, wc);
        float4 v0 = *(const float4*)&sxT[k][0];
        float4 v1 = *(const float4*)&sxT[k][4];
        float4 v2 = *(const float4*)&sxT[k][8];
        float4 v3 = *(const float4*)&sxT[k][12];
        unsigned long long a0 = pack2(v0.x, v0.y), a1 = pack2(v0.z, v0.w);
        unsigned long long a2 = pack2(v1.x, v1.y), a3 = pack2(v1.z, v1.w);
        unsigned long long a4 = pack2(v2.x, v2.y), a5 = pack2(v2.z, v2.w);
        unsigned long long a6 = pack2(v3.x, v3.y), a7 = pack2(v3.z, v3.w);
        fma2(aP2[0], a0, wp2); fma2(aC2[0], a0, wc2);
        fma2(aP2[1], a1, wp2); fma2(aC2[1], a1, wc2);
        fma2(aP2[2], a2, wp2); fma2(aC2[2], a2, wc2);
        fma2(aP2[3], a3, wp2); fma2(aC2[3], a3, wc2);
        fma2(aP2[4], a4, wp2); fma2(aC2[4], a4, wc2);
        fma2(aP2[5], a5, wp2); fma2(aC2[5], a5, wc2);
        fma2(aP2[6], a6, wp2); fma2(aC2[6], a6, wc2);
        fma2(aP2[7], a7, wp2); fma2(aC2[7], a7, wc2);
    }

    float aP[RPB], aC[RPB];
#pragma unroll
    for (int p = 0; p < 8; p++) {
        float2 fp = unpack2(aP2[p]); aP[2*p] = fp.x; aP[2*p+1] = fp.y;
        float2 fc = unpack2(aC2[p]); aC[2*p] = fc.x; aC[2*p+1] = fc.y;
    }

#pragma unroll
    for (int r = 0; r < RPB; r++) {
        g_hp16[(r0 + r) * DIM + j] = __float2half_rn(aP[r]);
        g_hc16[(r0 + r) * DIM + j] = __float2half_rn(aC[r]);
    }

    // alpha_src / alpha_dst dot products (4 scalars per row) — fp32 exact
    float asj = apS[j], adj = apD[j], csj = acS[j], cdj = acD[j];
    const int w = j >> 5, l = j & 31;
#pragma unroll
    for (int r = 0; r < RPB; r++) {
        float v0 = aP[r] * asj, v1 = aP[r] * adj, v2 = aC[r] * csj, v3 = aC[r] * cdj;
#pragma unroll
        for (int o = 16; o; o >>= 1) {
            v0 += __shfl_xor_sync(0xffffffffu, v0, o);
            v1 += __shfl_xor_sync(0xffffffffu, v1, o);
            v2 += __shfl_xor_sync(0xffffffffu, v2, o);
            v3 += __shfl_xor_sync(0xffffffffu, v3, o);
        }
        if (l == 0) {
            spart[w][r*4+0] = v0; spart[w][r*4+1] = v1;
            spart[w][r*4+2] = v2; spart[w][r*4+3] = v3;
        }
    }
    __syncthreads();
    if (j < RPB * 4) {
        float s = spart[0][j] + spart[1][j] + spart[2][j] + spart[3][j];
        int r = j >> 2, which = j & 3;
        int i = r0 + r;
        if      (which == 0) g_asp[i] = s;
        else if (which == 1) g_adp[i] = s;
        else if (which == 2) g_asc[i] = s;
        else                 g_adc[i] = s;
    }
}

// ---------------- K_agg: chunked warp-cooperative fp16 gather ------------------
// blockIdx.y: 0 = GAT parent, 1 = GAT child, 2 = SAGE(mean of x)
// Softmax without max-shift: exp(e)/sum(exp(e)); |e| small, fp32 safe.
__global__ void __launch_bounds__(256) k_agg()
{
    const int which = blockIdx.y;
    const int node  = (blockIdx.x * 256 + threadIdx.x) >> 5;   // 6250*8 = 50000 exact
    const int lane  = threadIdx.x & 31;

    const int* rp  = g_rp3[which];
    const int* csr = (which == 0) ? g_csrP : (which == 1) ? g_csrC : g_csrS;
    const __half* h16 = (which == 0) ? g_hp16 : (which == 1) ? g_hc16 : g_x16;
    float* acc = (which == 0) ? g_accp : (which == 1) ? g_accc : g_accs;

    const int base = rp[node], end = rp[node + 1];
    float4 a;

    if (which < 2) {
        const float* as_ = which ? g_asc : g_asp;
        const float* ad_ = which ? g_adc : g_adp;
        const float ad_i = ad_[node];

        float den = __expf(lrelu(as_[node] + ad_i));   // self loop
        uint2 hvs = ((const uint2*)(h16 + (size_t)node * DIM))[lane];
        float4 fs = h2f4(hvs);
        a.x = den * fs.x; a.y = den * fs.y; a.z = den * fs.z; a.w = den * fs.w;

        for (int cs = base; cs < end; cs += 32) {
            int idx = cs + lane;
            bool vld = idx < end;
            int   s  = vld ? csr[idx] : 0;
            float ex = vld ? __expf(lrelu(as_[s] + ad_i)) : 0.f;
            float exs = ex;
#pragma unroll
            for (int o = 16; o; o >>= 1)
                exs += __shfl_xor_sync(0xffffffffu, exs, o);
            den += exs;
            const int n = min(32, end - cs);
#pragma unroll 4
            for (int t = 0; t < n; t++) {
                int   sb  = __shfl_sync(0xffffffffu, s,  t);
                float exb = __shfl_sync(0xffffffffu, ex, t);
                uint2 hv = ((const uint2*)(h16 + (size_t)sb * DIM))[lane];
                float4 f = h2f4(hv);
                a.x = fmaf(exb, f.x, a.x); a.y = fmaf(exb, f.y, a.y);
                a.z = fmaf(exb, f.z, a.z); a.w = fmaf(exb, f.w, a.w);
            }
        }
        float r = 1.f / den;
        a.x *= r; a.y *= r; a.z *= r; a.w *= r;
    } else {
        a = make_float4(0.f, 0.f, 0.f, 0.f);
        for (int cs = base; cs < end; cs += 32) {
            int idx = cs + lane;
            int s   = (idx < end) ? csr[idx] : 0;
            const int n = min(32, end - cs);
#pragma unroll 4
            for (int t = 0; t < n; t++) {
                int sb = __shfl_sync(0xffffffffu, s, t);
                uint2 xv = ((const uint2*)(h16 + (size_t)sb * DIM))[lane];
                float4 f = h2f4(xv);
                a.x += f.x; a.y += f.y; a.z += f.z; a.w += f.w;
            }
        }
        float r = 1.f / fmaxf((float)(end - base), 1.f);
        a.x *= r; a.y *= r; a.z *= r; a.w *= r;
    }
    ((float4*)(acc + (size_t)node * DIM))[lane] = a;
}

// ---------------- K_final: mean·Wn + x·Wr (f32x2) + combine -------------------
__global__ void __launch_bounds__(128) k_final(
    const float* __restrict__ x,
    const float* __restrict__ Wn, const float* __restrict__ Wr,
    const float* __restrict__ bp, const float* __restrict__ bc,
    const float* __restrict__ bs, float* __restrict__ out)
{
    __shared__ __align__(16) float sxT[DIM][TPAD];
    __shared__ __align__(16) float smT[DIM][TPAD];
    const int j  = threadIdx.x;
    const int r0 = blockIdx.x * RPB;

    for (int t = j; t < RPB * DIM; t += 128) {
        int r = t >> 7, c = t & 127;
        sxT[c][r] = x[r0 * DIM + t];
        smT[c][r] = g_accs[r0 * DIM + t];
    }
    __syncthreads();

    unsigned long long o3[8];
#pragma unroll
    for (int p = 0; p < 8; p++) o3[p] = 0ull;

#pragma unroll 4
    for (int k = 0; k < DIM; k++) {
        float wn = Wn[k * DIM + j];
        float wr = Wr[k * DIM + j];
        unsigned long long wn2 = pack2(wn, wn);
        unsigned long long wr2 = pack2(wr, wr);
        float4 xv0 = *(const float4*)&sxT[k][0];
        float4 xv1 = *(const float4*)&sxT[k][4];
        float4 xv2 = *(const float4*)&sxT[k][8];
        float4 xv3 = *(const float4*)&sxT[k][12];
        float4 mv0 = *(const float4*)&smT[k][0];
        float4 mv1 = *(const float4*)&smT[k][4];
        float4 mv2 = *(const float4*)&smT[k][8];
        float4 mv3 = *(const float4*)&smT[k][12];
        fma2(o3[0], pack2(xv0.x, xv0.y), wr2); fma2(o3[0], pack2(mv0.x, mv0.y), wn2);
        fma2(o3[1], pack2(xv0.z, xv0.w), wr2); fma2(o3[1], pack2(mv0.z, mv0.w), wn2);
        fma2(o3[2], pack2(xv1.x, xv1.y), wr2); fma2(o3[2], pack2(mv1.x, mv1.y), wn2);
        fma2(o3[3], pack2(xv1.z, xv1.w), wr2); fma2(o3[3], pack2(mv1.z, mv1.w), wn2);
        fma2(o3[4], pack2(xv2.x, xv2.y), wr2); fma2(o3[4], pack2(mv2.x, mv2.y), wn2);
        fma2(o3[5], pack2(xv2.z, xv2.w), wr2); fma2(o3[5], pack2(mv2.z, mv2.w), wn2);
        fma2(o3[6], pack2(xv3.x, xv3.y), wr2); fma2(o3[6], pack2(mv3.x, mv3.y), wn2);
        fma2(o3[7], pack2(xv3.z, xv3.w), wr2); fma2(o3[7], pack2(mv3.z, mv3.w), wn2);
    }

    const float bsum = bp[j] + bc[j] + bs[j];
#pragma unroll
    for (int p = 0; p < 8; p++) {
        float2 f = unpack2(o3[p]);
        int i0 = r0 + 2*p, i1 = i0 + 1;
        float u0 = g_accp[i0 * DIM + j] + g_accc[i0 * DIM + j] + f.x + bsum;
        float u1 = g_accp[i1 * DIM + j] + g_accc[i1 * DIM + j] + f.y + bsum;
        out[i0 * DIM + j] = u0 * (1.f / 3.f);
        out[i1 * DIM + j] = u1 * (1.f / 3.f);
    }
}

// ---------------- launch ------------------------------------------------------
extern "C" void kernel_launch(void* const* d_in, const int* in_sizes, int n_in,
                              void* d_out, int out_size)
{
    const float* x    = (const float*)d_in[0];
    const int*   eip  = (const int*)d_in[1];   // [2, E]: src then dst
    const int*   eic  = (const int*)d_in[2];
    const int*   eir  = (const int*)d_in[3];
    const float* gpW  = (const float*)d_in[4];
    const float* gpaS = (const float*)d_in[5];
    const float* gpaD = (const float*)d_in[6];
    const float* gpB  = (const float*)d_in[7];
    const float* gcW  = (const float*)d_in[8];
    const float* gcaS = (const float*)d_in[9];
    const float* gcaD = (const float*)d_in[10];
    const float* gcB  = (const float*)d_in[11];
    const float* sgWn = (const float*)d_in[12];
    const float* sgWr = (const float*)d_in[13];
    const float* sgB  = (const float*)d_in[14];
    float* out = (float*)d_out;

    // CSR build (counts start zeroed: static init on first run, k_scan re-zeroes thereafter)
    k_count<<<dim3(N_EDGES / 256, 3), 256>>>(eip + N_EDGES, eic + N_EDGES, eir + N_EDGES);
    k_scan<<<3, 1024>>>();
    k_fill<<<dim3(N_EDGES / 256, 3), 256>>>(eip, eip + N_EDGES,
                                            eic, eic + N_EDGES,
                                            eir, eir + N_EDGES);
    // features + attention scalars (launch #4 — ncu slot)
    k_feat<<<N_NODES / RPB, 128>>>(x, gpW, gcW, gpaS, gpaD, gcaS, gcaD);
    // fused per-dst aggregation (2 GATs + SAGE mean), fp16 gathers
    k_agg<<<dim3(N_NODES / 8, 3), 256>>>();
    // SAGE GEMMs + combine
    k_final<<<N_NODES / RPB, 128>>>(x, sgWn, sgWr, gpB, gcB, sgB, out);
}

// round 11
// speedup vs baseline: 1.1079x; 1.1079x over previous
// R10 resubmit — R8 kernel unchanged; R9+R10 benches failed on infra (container failed twice), no kernel signal.
#include <cuda_runtime.h>
#include <cuda_fp16.h>
#include <math.h>

#define N_NODES 50000
#define DIM     128
#define N_EDGES 800000
#define NEG_SLOPE 0.2f

// ---------------- scratch (device globals) ------------------------------------
__device__ __half g_x16[N_NODES * DIM];       // fp16 x (A operand + SAGE gather)
__device__ __half g_hp16[N_NODES * DIM];      // GAT-parent features
__device__ __half g_hc16[N_NODES * DIM];      // GAT-child features
__device__ __half g_accs16[N_NODES * DIM];    // SAGE mean (fp16, A operand for k_final)
__device__ __half g_Wp16t[DIM * DIM];         // transposed fp16 weights [n][k]
__device__ __half g_Wc16t[DIM * DIM];
__device__ __half g_Wn16t[DIM * DIM];
__device__ __half g_Wr16t[DIM * DIM];
__device__ float g_accp[N_NODES * DIM];
__device__ float g_accc[N_NODES * DIM];
__device__ float g_asp[N_NODES], g_adp[N_NODES];
__device__ float g_asc[N_NODES], g_adc[N_NODES];
__device__ int g_cnt3[3][N_NODES];            // zeroed at load; re-zeroed by k_scan each run
__device__ int g_rp3[3][N_NODES + 1];
__device__ int g_cur3[3][N_NODES];
__device__ int g_csrP[N_EDGES], g_csrC[N_EDGES], g_csrS[N_EDGES];

// ---------------- helpers -----------------------------------------------------
__device__ __forceinline__ float lrelu(float v) { return v > 0.f ? v : NEG_SLOPE * v; }

__device__ __forceinline__ float4 h2f4(uint2 v) {
    __half2 a = *reinterpret_cast<__half2*>(&v.x);
    __half2 b = *reinterpret_cast<__half2*>(&v.y);
    float2 fa = __half22float2(a), fb = __half22float2(b);
    return make_float4(fa.x, fa.y, fb.x, fb.y);
}

__device__ __forceinline__ void mma16816(float* c, const unsigned* a, unsigned b0, unsigned b1) {
    asm volatile(
        "mma.sync.aligned.m16n8k16.row.col.f32.f16.f16.f32 "
        "{%0,%1,%2,%3}, {%4,%5,%6,%7}, {%8,%9}, {%0,%1,%2,%3};"
        : "+f"(c[0]), "+f"(c[1]), "+f"(c[2]), "+f"(c[3])
        : "r"(a[0]), "r"(a[1]), "r"(a[2]), "r"(a[3]), "r"(b0), "r"(b1));
}

// ---------------- prep: fp16 conversions --------------------------------------
__global__ void __launch_bounds__(256) k_prepx(const float* __restrict__ x) {
    int i = blockIdx.x * 256 + threadIdx.x;        // half2 index; 3.2M total
    ((__half2*)g_x16)[i] = __floats2half2_rn(x[2 * i], x[2 * i + 1]);
}

__global__ void __launch_bounds__(256) k_prepw(
    const float* __restrict__ Wp, const float* __restrict__ Wc,
    const float* __restrict__ Wn, const float* __restrict__ Wr)
{
    int m = blockIdx.y;
    const float* W = (m == 0) ? Wp : (m == 1) ? Wc : (m == 2) ? Wn : Wr;
    __half* Wt = (m == 0) ? g_Wp16t : (m == 1) ? g_Wc16t : (m == 2) ? g_Wn16t : g_Wr16t;
    int idx = blockIdx.x * 256 + threadIdx.x;      // 16384 per matrix
    int k = idx >> 7, n = idx & 127;
    Wt[n * DIM + k] = __float2half_rn(W[idx]);
}

// ---------------- CSR build ---------------------------------------------------
__global__ void __launch_bounds__(256) k_count(
    const int* __restrict__ dP, const int* __restrict__ dC, const int* __restrict__ dS)
{
    int g = blockIdx.y;
    int e = blockIdx.x * 256 + threadIdx.x;
    const int* d = (g == 0) ? dP : (g == 1) ? dC : dS;
    atomicAdd(&g_cnt3[g][d[e]], 1);
}

__global__ void __launch_bounds__(1024) k_scan() {
    int g = blockIdx.x;
    int* cnt = g_cnt3[g];
    int* rp  = g_rp3[g];
    int* cur = g_cur3[g];
    const int CH = 49;  // 1024*49 = 50176 >= 50000
    int t = threadIdx.x, lane = t & 31, w = t >> 5;
    int base = t * CH;
    int s = 0;
    for (int i = 0; i < CH; i++) {
        int idx = base + i;
        if (idx < N_NODES) s += cnt[idx];
    }
    __shared__ int wsum[32];
    int v = s;
#pragma unroll
    for (int o = 1; o < 32; o <<= 1) {
        int u = __shfl_up_sync(0xffffffffu, v, o);
        if (lane >= o) v += u;
    }
    if (lane == 31) wsum[w] = v;
    __syncthreads();
    if (w == 0) {
        int z = wsum[lane];
#pragma unroll
        for (int o = 1; o < 32; o <<= 1) {
            int u = __shfl_up_sync(0xffffffffu, z, o);
            if (lane >= o) z += u;
        }
        wsum[lane] = z;
    }
    __syncthreads();
    int off = v - s + (w ? wsum[w - 1] : 0);
    int run = off;
    for (int i = 0; i < CH; i++) {
        int idx = base + i;
        if (idx < N_NODES) {
            rp[idx] = run; cur[idx] = run;
            run += cnt[idx];
            cnt[idx] = 0;   // restore invariant for graph replays
        }
    }
    if (t == 0) rp[N_NODES] = N_EDGES;
}

__global__ void __launch_bounds__(256) k_fill(
    const int* __restrict__ sP, const int* __restrict__ dP,
    const int* __restrict__ sC, const int* __restrict__ dC,
    const int* __restrict__ sS, const int* __restrict__ dS)
{
    int g = blockIdx.y;
    int e = blockIdx.x * 256 + threadIdx.x;
    const int* src = (g == 0) ? sP : (g == 1) ? sC : sS;
    const int* dst = (g == 0) ? dP : (g == 1) ? dC : dS;
    int* csr       = (g == 0) ? g_csrP : (g == 1) ? g_csrC : g_csrS;
    int pos = atomicAdd(&g_cur3[g][dst[e]], 1);
    csr[pos] = src[e];
}

// ---------------- K_feat: h = x·W via HMMA; alpha dots from fp32 acc ----------
// 8 warps/block: warps 0-3 -> Wp, warps 4-7 -> Wc, same 64 rows.
__global__ void __launch_bounds__(256) k_feat(
    const float* __restrict__ apS, const float* __restrict__ apD,
    const float* __restrict__ acS, const float* __restrict__ acD)
{
    const int w = threadIdx.x >> 5, lane = threadIdx.x & 31;
    const int mat = w >> 2;
    const int rA  = blockIdx.x * 64 + (w & 3) * 16 + (lane >> 2);
    const int rA0 = min(rA, N_NODES - 1);
    const int rA1 = min(rA + 8, N_NODES - 1);
    const int kc  = (lane & 3) * 2;
    const __half* Wt = mat ? g_Wc16t : g_Wp16t;
    __half* hout     = mat ? g_hc16  : g_hp16;

    float acc[16][4];
#pragma unroll
    for (int nt = 0; nt < 16; nt++) { acc[nt][0] = acc[nt][1] = acc[nt][2] = acc[nt][3] = 0.f; }

#pragma unroll 2
    for (int ks = 0; ks < 8; ks++) {
        const int k0 = ks * 16;
        unsigned a[4];
        a[0] = *(const unsigned*)(g_x16 + (size_t)rA0 * DIM + k0 + kc);
        a[1] = *(const unsigned*)(g_x16 + (size_t)rA1 * DIM + k0 + kc);
        a[2] = *(const unsigned*)(g_x16 + (size_t)rA0 * DIM + k0 + kc + 8);
        a[3] = *(const unsigned*)(g_x16 + (size_t)rA1 * DIM + k0 + kc + 8);
#pragma unroll
        for (int nt = 0; nt < 16; nt++) {
            const int n = nt * 8 + (lane >> 2);
            unsigned b0 = *(const unsigned*)(Wt + (size_t)n * DIM + k0 + kc);
            unsigned b1 = *(const unsigned*)(Wt + (size_t)n * DIM + k0 + kc + 8);
            mma16816(acc[nt], a, b0, b1);
        }
    }

    // epilogue: store fp16 h rows + fp32 alpha dot products
    const float* aS = mat ? acS : apS;
    const float* aD = mat ? acD : apD;
    float dS0 = 0.f, dD0 = 0.f, dS1 = 0.f, dD1 = 0.f;
    const bool ok0 = rA < N_NODES, ok1 = (rA + 8) < N_NODES;
#pragma unroll
    for (int nt = 0; nt < 16; nt++) {
        const int c0 = nt * 8 + (lane & 3) * 2;
        float s0 = aS[c0], s1 = aS[c0 + 1], d0 = aD[c0], d1 = aD[c0 + 1];
        dS0 += acc[nt][0] * s0 + acc[nt][1] * s1;
        dD0 += acc[nt][0] * d0 + acc[nt][1] * d1;
        dS1 += acc[nt][2] * s0 + acc[nt][3] * s1;
        dD1 += acc[nt][2] * d0 + acc[nt][3] * d1;
        if (ok0) *(__half2*)(hout + (size_t)rA * DIM + c0)       = __floats2half2_rn(acc[nt][0], acc[nt][1]);
        if (ok1) *(__half2*)(hout + (size_t)(rA + 8) * DIM + c0) = __floats2half2_rn(acc[nt][2], acc[nt][3]);
    }
    // reduce over the 4 lanes sharing each row (lane groups of 4)
    dS0 += __shfl_xor_sync(0xffffffffu, dS0, 1); dS0 += __shfl_xor_sync(0xffffffffu, dS0, 2);
    dD0 += __shfl_xor_sync(0xffffffffu, dD0, 1); dD0 += __shfl_xor_sync(0xffffffffu, dD0, 2);
    dS1 += __shfl_xor_sync(0xffffffffu, dS1, 1); dS1 += __shfl_xor_sync(0xffffffffu, dS1, 2);
    dD1 += __shfl_xor_sync(0xffffffffu, dD1, 1); dD1 += __shfl_xor_sync(0xffffffffu, dD1, 2);
    if ((lane & 3) == 0) {
        float* asO = mat ? g_asc : g_asp;
        float* adO = mat ? g_adc : g_adp;
        if (ok0) { asO[rA] = dS0;     adO[rA] = dD0; }
        if (ok1) { asO[rA + 8] = dS1; adO[rA + 8] = dD1; }
    }
}

// ---------------- K_agg: chunked warp-cooperative fp16 gather ------------------
// blockIdx.y: 0 = GAT parent, 1 = GAT child, 2 = SAGE(mean of x)
// Maxless softmax: exp(e)/sum(exp(e)); |e| small, fp32 safe.
__global__ void __launch_bounds__(256) k_agg()
{
    const int which = blockIdx.y;
    const int node  = (blockIdx.x * 256 + threadIdx.x) >> 5;   // 6250*8 = 50000 exact
    const int lane  = threadIdx.x & 31;

    const int* rp  = g_rp3[which];
    const int* csr = (which == 0) ? g_csrP : (which == 1) ? g_csrC : g_csrS;
    const __half* h16 = (which == 0) ? g_hp16 : (which == 1) ? g_hc16 : g_x16;

    const int base = rp[node], end = rp[node + 1];
    float4 a;

    if (which < 2) {
        const float* as_ = which ? g_asc : g_asp;
        const float* ad_ = which ? g_adc : g_adp;
        const float ad_i = ad_[node];

        float den = __expf(lrelu(as_[node] + ad_i));   // self loop
        uint2 hvs = ((const uint2*)(h16 + (size_t)node * DIM))[lane];
        float4 fs = h2f4(hvs);
        a.x = den * fs.x; a.y = den * fs.y; a.z = den * fs.z; a.w = den * fs.w;

        for (int cs = base; cs < end; cs += 32) {
            int idx = cs + lane;
            bool vld = idx < end;
            int   s  = vld ? csr[idx] : 0;
            float ex = vld ? __expf(lrelu(as_[s] + ad_i)) : 0.f;
            float exs = ex;
#pragma unroll
            for (int o = 16; o; o >>= 1)
                exs += __shfl_xor_sync(0xffffffffu, exs, o);
            den += exs;
            const int n = min(32, end - cs);
#pragma unroll 4
            for (int t = 0; t < n; t++) {
                int   sb  = __shfl_sync(0xffffffffu, s,  t);
                float exb = __shfl_sync(0xffffffffu, ex, t);
                uint2 hv = ((const uint2*)(h16 + (size_t)sb * DIM))[lane];
                float4 f = h2f4(hv);
                a.x = fmaf(exb, f.x, a.x); a.y = fmaf(exb, f.y, a.y);
                a.z = fmaf(exb, f.z, a.z); a.w = fmaf(exb, f.w, a.w);
            }
        }
        float r = 1.f / den;
        a.x *= r; a.y *= r; a.z *= r; a.w *= r;
        float* acc = which ? g_accc : g_accp;
        ((float4*)(acc + (size_t)node * DIM))[lane] = a;
    } else {
        a = make_float4(0.f, 0.f, 0.f, 0.f);
        for (int cs = base; cs < end; cs += 32) {
            int idx = cs + lane;
            int s   = (idx < end) ? csr[idx] : 0;
            const int n = min(32, end - cs);
#pragma unroll 4
            for (int t = 0; t < n; t++) {
                int sb = __shfl_sync(0xffffffffu, s, t);
                uint2 xv = ((const uint2*)(h16 + (size_t)sb * DIM))[lane];
                float4 f = h2f4(xv);
                a.x += f.x; a.y += f.y; a.z += f.z; a.w += f.w;
            }
        }
        float r = 1.f / fmaxf((float)(end - base), 1.f);
        // fp16 mean for k_final's A operand
        uint2 pk;
        *reinterpret_cast<__half2*>(&pk.x) = __floats2half2_rn(a.x * r, a.y * r);
        *reinterpret_cast<__half2*>(&pk.y) = __floats2half2_rn(a.z * r, a.w * r);
        ((uint2*)(g_accs16 + (size_t)node * DIM))[lane] = pk;
    }
}

// ---------------- K_final: mean·Wn + x·Wr via HMMA + combine ------------------
// 4 warps/block, 16 rows each.
__global__ void __launch_bounds__(128) k_final(
    const float* __restrict__ bp, const float* __restrict__ bc,
    const float* __restrict__ bs, float* __restrict__ out)
{
    const int w = threadIdx.x >> 5, lane = threadIdx.x & 31;
    const int rA  = blockIdx.x * 64 + w * 16 + (lane >> 2);
    const int rA0 = min(rA, N_NODES - 1);
    const int rA1 = min(rA + 8, N_NODES - 1);
    const int kc  = (lane & 3) * 2;

    float acc[16][4];
#pragma unroll
    for (int nt = 0; nt < 16; nt++) { acc[nt][0] = acc[nt][1] = acc[nt][2] = acc[nt][3] = 0.f; }

    // chain 1: mean(accs16) · Wn
#pragma unroll 2
    for (int ks = 0; ks < 8; ks++) {
        const int k0 = ks * 16;
        unsigned a[4];
        a[0] = *(const unsigned*)(g_accs16 + (size_t)rA0 * DIM + k0 + kc);
        a[1] = *(const unsigned*)(g_accs16 + (size_t)rA1 * DIM + k0 + kc);
        a[2] = *(const unsigned*)(g_accs16 + (size_t)rA0 * DIM + k0 + kc + 8);
        a[3] = *(const unsigned*)(g_accs16 + (size_t)rA1 * DIM + k0 + kc + 8);
#pragma unroll
        for (int nt = 0; nt < 16; nt++) {
            const int n = nt * 8 + (lane >> 2);
            unsigned b0 = *(const unsigned*)(g_Wn16t + (size_t)n * DIM + k0 + kc);
            unsigned b1 = *(const unsigned*)(g_Wn16t + (size_t)n * DIM + k0 + kc + 8);
            mma16816(acc[nt], a, b0, b1);
        }
    }
    // chain 2: x · Wr (same accumulators)
#pragma unroll 2
    for (int ks = 0; ks < 8; ks++) {
        const int k0 = ks * 16;
        unsigned a[4];
        a[0] = *(const unsigned*)(g_x16 + (size_t)rA0 * DIM + k0 + kc);
        a[1] = *(const unsigned*)(g_x16 + (size_t)rA1 * DIM + k0 + kc);
        a[2] = *(const unsigned*)(g_x16 + (size_t)rA0 * DIM + k0 + kc + 8);
        a[3] = *(const unsigned*)(g_x16 + (size_t)rA1 * DIM + k0 + kc + 8);
#pragma unroll
        for (int nt = 0; nt < 16; nt++) {
            const int n = nt * 8 + (lane >> 2);
            unsigned b0 = *(const unsigned*)(g_Wr16t + (size_t)n * DIM + k0 + kc);
            unsigned b1 = *(const unsigned*)(g_Wr16t + (size_t)n * DIM + k0 + kc + 8);
            mma16816(acc[nt], a, b0, b1);
        }
    }

    const bool ok0 = rA < N_NODES, ok1 = (rA + 8) < N_NODES;
#pragma unroll
    for (int nt = 0; nt < 16; nt++) {
        const int c0 = nt * 8 + (lane & 3) * 2;
        float b0 = bp[c0] + bc[c0] + bs[c0];
        float b1 = bp[c0 + 1] + bc[c0 + 1] + bs[c0 + 1];
        if (ok0) {
            float2 p = *(const float2*)(g_accp + (size_t)rA * DIM + c0);
            float2 c = *(const float2*)(g_accc + (size_t)rA * DIM + c0);
            float2 o;
            o.x = (acc[nt][0] + p.x + c.x + b0) * (1.f / 3.f);
            o.y = (acc[nt][1] + p.y + c.y + b1) * (1.f / 3.f);
            *(float2*)(out + (size_t)rA * DIM + c0) = o;
        }
        if (ok1) {
            float2 p = *(const float2*)(g_accp + (size_t)(rA + 8) * DIM + c0);
            float2 c = *(const float2*)(g_accc + (size_t)(rA + 8) * DIM + c0);
            float2 o;
            o.x = (acc[nt][2] + p.x + c.x + b0) * (1.f / 3.f);
            o.y = (acc[nt][3] + p.y + c.y + b1) * (1.f / 3.f);
            *(float2*)(out + (size_t)(rA + 8) * DIM + c0) = o;
        }
    }
}

// ---------------- launch ------------------------------------------------------
extern "C" void kernel_launch(void* const* d_in, const int* in_sizes, int n_in,
                              void* d_out, int out_size)
{
    const float* x    = (const float*)d_in[0];
    const int*   eip  = (const int*)d_in[1];   // [2, E]: src then dst
    const int*   eic  = (const int*)d_in[2];
    const int*   eir  = (const int*)d_in[3];
    const float* gpW  = (const float*)d_in[4];
    const float* gpaS = (const float*)d_in[5];
    const float* gpaD = (const float*)d_in[6];
    const float* gpB  = (const float*)d_in[7];
    const float* gcW  = (const float*)d_in[8];
    const float* gcaS = (const float*)d_in[9];
    const float* gcaD = (const float*)d_in[10];
    const float* gcB  = (const float*)d_in[11];
    const float* sgWn = (const float*)d_in[12];
    const float* sgWr = (const float*)d_in[13];
    const float* sgB  = (const float*)d_in[14];
    float* out = (float*)d_out;

    // fp16 prep
    k_prepx<<<(N_NODES * DIM / 2) / 256, 256>>>(x);
    k_prepw<<<dim3(64, 4), 256>>>(gpW, gcW, sgWn, sgWr);
    // CSR build
    k_count<<<dim3(N_EDGES / 256, 3), 256>>>(eip + N_EDGES, eic + N_EDGES, eir + N_EDGES);
    k_scan<<<3, 1024>>>();
    k_fill<<<dim3(N_EDGES / 256, 3), 256>>>(eip, eip + N_EDGES,
                                            eic, eic + N_EDGES,
                                            eir, eir + N_EDGES);
    // tensor-core feature GEMMs + alpha scalars
    k_feat<<<782, 256>>>(gpaS, gpaD, gcaS, gcaD);
    // per-dst aggregation (2 GATs + SAGE mean)
    k_agg<<<dim3(N_NODES / 8, 3), 256>>>();
    // tensor-core SAGE GEMMs + combine
    k_final<<<782, 128>>>(gpB, gcB, sgB, out);
}

// round 12
// speedup vs baseline: 1.4521x; 1.3108x over previous
// R11: replace serial k_scan (110.9us, grid=3!) with warp-aggregated atomic segment alloc; k_agg unroll 8.
#include <cuda_runtime.h>
#include <cuda_fp16.h>
#include <math.h>

#define N_NODES 50000
#define DIM     128
#define N_EDGES 800000
#define NEG_SLOPE 0.2f

// ---------------- scratch (device globals) ------------------------------------
__device__ __half g_x16[N_NODES * DIM];       // fp16 x (A operand + SAGE gather)
__device__ __half g_hp16[N_NODES * DIM];      // GAT-parent features
__device__ __half g_hc16[N_NODES * DIM];      // GAT-child features
__device__ __half g_accs16[N_NODES * DIM];    // SAGE mean (fp16, A operand for k_final)
__device__ __half g_Wp16t[DIM * DIM];         // transposed fp16 weights [n][k]
__device__ __half g_Wc16t[DIM * DIM];
__device__ __half g_Wn16t[DIM * DIM];
__device__ __half g_Wr16t[DIM * DIM];
__device__ float g_accp[N_NODES * DIM];
__device__ float g_accc[N_NODES * DIM];
__device__ float g_asp[N_NODES], g_adp[N_NODES];
__device__ float g_asc[N_NODES], g_adc[N_NODES];
__device__ int g_cnt3[3][N_NODES];            // zeroed at load; re-zeroed by k_alloc each run
__device__ int g_rp3[3][N_NODES];             // segment start (NOT monotone across nodes)
__device__ int g_rpe3[3][N_NODES];            // segment end
__device__ int g_cur3[3][N_NODES];
__device__ int g_base3[3];                    // bump allocators; reset by k_count
__device__ int g_csrP[N_EDGES], g_csrC[N_EDGES], g_csrS[N_EDGES];

// ---------------- helpers -----------------------------------------------------
__device__ __forceinline__ float lrelu(float v) { return v > 0.f ? v : NEG_SLOPE * v; }

__device__ __forceinline__ float4 h2f4(uint2 v) {
    __half2 a = *reinterpret_cast<__half2*>(&v.x);
    __half2 b = *reinterpret_cast<__half2*>(&v.y);
    float2 fa = __half22float2(a), fb = __half22float2(b);
    return make_float4(fa.x, fa.y, fb.x, fb.y);
}

__device__ __forceinline__ void mma16816(float* c, const unsigned* a, unsigned b0, unsigned b1) {
    asm volatile(
        "mma.sync.aligned.m16n8k16.row.col.f32.f16.f16.f32 "
        "{%0,%1,%2,%3}, {%4,%5,%6,%7}, {%8,%9}, {%0,%1,%2,%3};"
        : "+f"(c[0]), "+f"(c[1]), "+f"(c[2]), "+f"(c[3])
        : "r"(a[0]), "r"(a[1]), "r"(a[2]), "r"(a[3]), "r"(b0), "r"(b1));
}

// ---------------- prep: fp16 conversions --------------------------------------
__global__ void __launch_bounds__(256) k_prepx(const float* __restrict__ x) {
    int i = blockIdx.x * 256 + threadIdx.x;        // half2 index; 3.2M total
    ((__half2*)g_x16)[i] = __floats2half2_rn(x[2 * i], x[2 * i + 1]);
}

__global__ void __launch_bounds__(256) k_prepw(
    const float* __restrict__ Wp, const float* __restrict__ Wc,
    const float* __restrict__ Wn, const float* __restrict__ Wr)
{
    int m = blockIdx.y;
    const float* W = (m == 0) ? Wp : (m == 1) ? Wc : (m == 2) ? Wn : Wr;
    __half* Wt = (m == 0) ? g_Wp16t : (m == 1) ? g_Wc16t : (m == 2) ? g_Wn16t : g_Wr16t;
    int idx = blockIdx.x * 256 + threadIdx.x;      // 16384 per matrix
    int k = idx >> 7, n = idx & 127;
    Wt[n * DIM + k] = __float2half_rn(W[idx]);
}

// ---------------- CSR build ---------------------------------------------------
__global__ void __launch_bounds__(256) k_count(
    const int* __restrict__ dP, const int* __restrict__ dC, const int* __restrict__ dS)
{
    int g = blockIdx.y;
    if (blockIdx.x == 0 && threadIdx.x == 0) g_base3[g] = 0;   // reset bump allocator
    int e = blockIdx.x * 256 + threadIdx.x;
    const int* d = (g == 0) ? dP : (g == 1) ? dC : dS;
    atomicAdd(&g_cnt3[g][d[e]], 1);
}

// Segment allocation: per-node private range via warp-aggregated bump atomics.
// No ordering across nodes is required by k_agg, so no global prefix scan.
__global__ void __launch_bounds__(256) k_alloc() {
    int g = blockIdx.y;
    int i = blockIdx.x * 256 + threadIdx.x;        // 196*256 = 50176 >= 50000
    int lane = threadIdx.x & 31;
    int deg = (i < N_NODES) ? g_cnt3[g][i] : 0;
    int s = deg;
#pragma unroll
    for (int o = 1; o < 32; o <<= 1) {
        int u = __shfl_up_sync(0xffffffffu, s, o);
        if (lane >= o) s += u;
    }
    int total = __shfl_sync(0xffffffffu, s, 31);
    int base0 = 0;
    if (lane == 0) base0 = atomicAdd(&g_base3[g], total);
    base0 = __shfl_sync(0xffffffffu, base0, 0);
    int mybase = base0 + s - deg;
    if (i < N_NODES) {
        g_rp3[g][i]  = mybase;
        g_rpe3[g][i] = mybase + deg;
        g_cur3[g][i] = mybase;
        g_cnt3[g][i] = 0;                          // restore invariant for graph replays
    }
}

__global__ void __launch_bounds__(256) k_fill(
    const int* __restrict__ sP, const int* __restrict__ dP,
    const int* __restrict__ sC, const int* __restrict__ dC,
    const int* __restrict__ sS, const int* __restrict__ dS)
{
    int g = blockIdx.y;
    int e = blockIdx.x * 256 + threadIdx.x;
    const int* src = (g == 0) ? sP : (g == 1) ? sC : sS;
    const int* dst = (g == 0) ? dP : (g == 1) ? dC : dS;
    int* csr       = (g == 0) ? g_csrP : (g == 1) ? g_csrC : g_csrS;
    int pos = atomicAdd(&g_cur3[g][dst[e]], 1);
    csr[pos] = src[e];
}

// ---------------- K_feat: h = x·W via HMMA; alpha dots from fp32 acc ----------
// 8 warps/block: warps 0-3 -> Wp, warps 4-7 -> Wc, same 64 rows.
__global__ void __launch_bounds__(256) k_feat(
    const float* __restrict__ apS, const float* __restrict__ apD,
    const float* __restrict__ acS, const float* __restrict__ acD)
{
    const int w = threadIdx.x >> 5, lane = threadIdx.x & 31;
    const int mat = w >> 2;
    const int rA  = blockIdx.x * 64 + (w & 3) * 16 + (lane >> 2);
    const int rA0 = min(rA, N_NODES - 1);
    const int rA1 = min(rA + 8, N_NODES - 1);
    const int kc  = (lane & 3) * 2;
    const __half* Wt = mat ? g_Wc16t : g_Wp16t;
    __half* hout     = mat ? g_hc16  : g_hp16;

    float acc[16][4];
#pragma unroll
    for (int nt = 0; nt < 16; nt++) { acc[nt][0] = acc[nt][1] = acc[nt][2] = acc[nt][3] = 0.f; }

#pragma unroll 2
    for (int ks = 0; ks < 8; ks++) {
        const int k0 = ks * 16;
        unsigned a[4];
        a[0] = *(const unsigned*)(g_x16 + (size_t)rA0 * DIM + k0 + kc);
        a[1] = *(const unsigned*)(g_x16 + (size_t)rA1 * DIM + k0 + kc);
        a[2] = *(const unsigned*)(g_x16 + (size_t)rA0 * DIM + k0 + kc + 8);
        a[3] = *(const unsigned*)(g_x16 + (size_t)rA1 * DIM + k0 + kc + 8);
#pragma unroll
        for (int nt = 0; nt < 16; nt++) {
            const int n = nt * 8 + (lane >> 2);
            unsigned b0 = *(const unsigned*)(Wt + (size_t)n * DIM + k0 + kc);
            unsigned b1 = *(const unsigned*)(Wt + (size_t)n * DIM + k0 + kc + 8);
            mma16816(acc[nt], a, b0, b1);
        }
    }

    // epilogue: store fp16 h rows + fp32 alpha dot products
    const float* aS = mat ? acS : apS;
    const float* aD = mat ? acD : apD;
    float dS0 = 0.f, dD0 = 0.f, dS1 = 0.f, dD1 = 0.f;
    const bool ok0 = rA < N_NODES, ok1 = (rA + 8) < N_NODES;
#pragma unroll
    for (int nt = 0; nt < 16; nt++) {
        const int c0 = nt * 8 + (lane & 3) * 2;
        float s0 = aS[c0], s1 = aS[c0 + 1], d0 = aD[c0], d1 = aD[c0 + 1];
        dS0 += acc[nt][0] * s0 + acc[nt][1] * s1;
        dD0 += acc[nt][0] * d0 + acc[nt][1] * d1;
        dS1 += acc[nt][2] * s0 + acc[nt][3] * s1;
        dD1 += acc[nt][2] * d0 + acc[nt][3] * d1;
        if (ok0) *(__half2*)(hout + (size_t)rA * DIM + c0)       = __floats2half2_rn(acc[nt][0], acc[nt][1]);
        if (ok1) *(__half2*)(hout + (size_t)(rA + 8) * DIM + c0) = __floats2half2_rn(acc[nt][2], acc[nt][3]);
    }
    // reduce over the 4 lanes sharing each row (lane groups of 4)
    dS0 += __shfl_xor_sync(0xffffffffu, dS0, 1); dS0 += __shfl_xor_sync(0xffffffffu, dS0, 2);
    dD0 += __shfl_xor_sync(0xffffffffu, dD0, 1); dD0 += __shfl_xor_sync(0xffffffffu, dD0, 2);
    dS1 += __shfl_xor_sync(0xffffffffu, dS1, 1); dS1 += __shfl_xor_sync(0xffffffffu, dS1, 2);
    dD1 += __shfl_xor_sync(0xffffffffu, dD1, 1); dD1 += __shfl_xor_sync(0xffffffffu, dD1, 2);
    if ((lane & 3) == 0) {
        float* asO = mat ? g_asc : g_asp;
        float* adO = mat ? g_adc : g_adp;
        if (ok0) { asO[rA] = dS0;     adO[rA] = dD0; }
        if (ok1) { asO[rA + 8] = dS1; adO[rA + 8] = dD1; }
    }
}

// ---------------- K_agg: chunked warp-cooperative fp16 gather ------------------
// blockIdx.y: 0 = GAT parent, 1 = GAT child, 2 = SAGE(mean of x)
// Maxless softmax: exp(e)/sum(exp(e)); |e| small, fp32 safe.
__global__ void __launch_bounds__(256) k_agg()
{
    const int which = blockIdx.y;
    const int node  = (blockIdx.x * 256 + threadIdx.x) >> 5;   // 6250*8 = 50000 exact
    const int lane  = threadIdx.x & 31;

    const int* csr = (which == 0) ? g_csrP : (which == 1) ? g_csrC : g_csrS;
    const __half* h16 = (which == 0) ? g_hp16 : (which == 1) ? g_hc16 : g_x16;

    const int base = g_rp3[which][node], end = g_rpe3[which][node];
    float4 a;

    if (which < 2) {
        const float* as_ = which ? g_asc : g_asp;
        const float* ad_ = which ? g_adc : g_adp;
        const float ad_i = ad_[node];

        float den = __expf(lrelu(as_[node] + ad_i));   // self loop
        uint2 hvs = ((const uint2*)(h16 + (size_t)node * DIM))[lane];
        float4 fs = h2f4(hvs);
        a.x = den * fs.x; a.y = den * fs.y; a.z = den * fs.z; a.w = den * fs.w;

        for (int cs = base; cs < end; cs += 32) {
            int idx = cs + lane;
            bool vld = idx < end;
            int   s  = vld ? csr[idx] : 0;
            float ex = vld ? __expf(lrelu(as_[s] + ad_i)) : 0.f;
            float exs = ex;
#pragma unroll
            for (int o = 16; o; o >>= 1)
                exs += __shfl_xor_sync(0xffffffffu, exs, o);
            den += exs;
            const int n = min(32, end - cs);
#pragma unroll 8
            for (int t = 0; t < n; t++) {
                int   sb  = __shfl_sync(0xffffffffu, s,  t);
                float exb = __shfl_sync(0xffffffffu, ex, t);
                uint2 hv = ((const uint2*)(h16 + (size_t)sb * DIM))[lane];
                float4 f = h2f4(hv);
                a.x = fmaf(exb, f.x, a.x); a.y = fmaf(exb, f.y, a.y);
                a.z = fmaf(exb, f.z, a.z); a.w = fmaf(exb, f.w, a.w);
            }
        }
        float r = 1.f / den;
        a.x *= r; a.y *= r; a.z *= r; a.w *= r;
        float* acc = which ? g_accc : g_accp;
        ((float4*)(acc + (size_t)node * DIM))[lane] = a;
    } else {
        a = make_float4(0.f, 0.f, 0.f, 0.f);
        for (int cs = base; cs < end; cs += 32) {
            int idx = cs + lane;
            int s   = (idx < end) ? csr[idx] : 0;
            const int n = min(32, end - cs);
#pragma unroll 8
            for (int t = 0; t < n; t++) {
                int sb = __shfl_sync(0xffffffffu, s, t);
                uint2 xv = ((const uint2*)(h16 + (size_t)sb * DIM))[lane];
                float4 f = h2f4(xv);
                a.x += f.x; a.y += f.y; a.z += f.z; a.w += f.w;
            }
        }
        float r = 1.f / fmaxf((float)(end - base), 1.f);
        // fp16 mean for k_final's A operand
        uint2 pk;
        *reinterpret_cast<__half2*>(&pk.x) = __floats2half2_rn(a.x * r, a.y * r);
        *reinterpret_cast<__half2*>(&pk.y) = __floats2half2_rn(a.z * r, a.w * r);
        ((uint2*)(g_accs16 + (size_t)node * DIM))[lane] = pk;
    }
}

// ---------------- K_final: mean·Wn + x·Wr via HMMA + combine ------------------
// 4 warps/block, 16 rows each.
__global__ void __launch_bounds__(128) k_final(
    const float* __restrict__ bp, const float* __restrict__ bc,
    const float* __restrict__ bs, float* __restrict__ out)
{
    const int w = threadIdx.x >> 5, lane = threadIdx.x & 31;
    const int rA  = blockIdx.x * 64 + w * 16 + (lane >> 2);
    const int rA0 = min(rA, N_NODES - 1);
    const int rA1 = min(rA + 8, N_NODES - 1);
    const int kc  = (lane & 3) * 2;

    float acc[16][4];
#pragma unroll
    for (int nt = 0; nt < 16; nt++) { acc[nt][0] = acc[nt][1] = acc[nt][2] = acc[nt][3] = 0.f; }

    // chain 1: mean(accs16) · Wn
#pragma unroll 2
    for (int ks = 0; ks < 8; ks++) {
        const int k0 = ks * 16;
        unsigned a[4];
        a[0] = *(const unsigned*)(g_accs16 + (size_t)rA0 * DIM + k0 + kc);
        a[1] = *(const unsigned*)(g_accs16 + (size_t)rA1 * DIM + k0 + kc);
        a[2] = *(const unsigned*)(g_accs16 + (size_t)rA0 * DIM + k0 + kc + 8);
        a[3] = *(const unsigned*)(g_accs16 + (size_t)rA1 * DIM + k0 + kc + 8);
#pragma unroll
        for (int nt = 0; nt < 16; nt++) {
            const int n = nt * 8 + (lane >> 2);
            unsigned b0 = *(const unsigned*)(g_Wn16t + (size_t)n * DIM + k0 + kc);
            unsigned b1 = *(const unsigned*)(g_Wn16t + (size_t)n * DIM + k0 + kc + 8);
            mma16816(acc[nt], a, b0, b1);
        }
    }
    // chain 2: x · Wr (same accumulators)
#pragma unroll 2
    for (int ks = 0; ks < 8; ks++) {
        const int k0 = ks * 16;
        unsigned a[4];
        a[0] = *(const unsigned*)(g_x16 + (size_t)rA0 * DIM + k0 + kc);
        a[1] = *(const unsigned*)(g_x16 + (size_t)rA1 * DIM + k0 + kc);
        a[2] = *(const unsigned*)(g_x16 + (size_t)rA0 * DIM + k0 + kc + 8);
        a[3] = *(const unsigned*)(g_x16 + (size_t)rA1 * DIM + k0 + kc + 8);
#pragma unroll
        for (int nt = 0; nt < 16; nt++) {
            const int n = nt * 8 + (lane >> 2);
            unsigned b0 = *(const unsigned*)(g_Wr16t + (size_t)n * DIM + k0 + kc);
            unsigned b1 = *(const unsigned*)(g_Wr16t + (size_t)n * DIM + k0 + kc + 8);
            mma16816(acc[nt], a, b0, b1);
        }
    }

    const bool ok0 = rA < N_NODES, ok1 = (rA + 8) < N_NODES;
#pragma unroll
    for (int nt = 0; nt < 16; nt++) {
        const int c0 = nt * 8 + (lane & 3) * 2;
        float b0 = bp[c0] + bc[c0] + bs[c0];
        float b1 = bp[c0 + 1] + bc[c0 + 1] + bs[c0 + 1];
        if (ok0) {
            float2 p = *(const float2*)(g_accp + (size_t)rA * DIM + c0);
            float2 c = *(const float2*)(g_accc + (size_t)rA * DIM + c0);
            float2 o;
            o.x = (acc[nt][0] + p.x + c.x + b0) * (1.f / 3.f);
            o.y = (acc[nt][1] + p.y + c.y + b1) * (1.f / 3.f);
            *(float2*)(out + (size_t)rA * DIM + c0) = o;
        }
        if (ok1) {
            float2 p = *(const float2*)(g_accp + (size_t)(rA + 8) * DIM + c0);
            float2 c = *(const float2*)(g_accc + (size_t)(rA + 8) * DIM + c0);
            float2 o;
            o.x = (acc[nt][2] + p.x + c.x + b0) * (1.f / 3.f);
            o.y = (acc[nt][3] + p.y + c.y + b1) * (1.f / 3.f);
            *(float2*)(out + (size_t)(rA + 8) * DIM + c0) = o;
        }
    }
}

// ---------------- launch ------------------------------------------------------
extern "C" void kernel_launch(void* const* d_in, const int* in_sizes, int n_in,
                              void* d_out, int out_size)
{
    const float* x    = (const float*)d_in[0];
    const int*   eip  = (const int*)d_in[1];   // [2, E]: src then dst
    const int*   eic  = (const int*)d_in[2];
    const int*   eir  = (const int*)d_in[3];
    const float* gpW  = (const float*)d_in[4];
    const float* gpaS = (const float*)d_in[5];
    const float* gpaD = (const float*)d_in[6];
    const float* gpB  = (const float*)d_in[7];
    const float* gcW  = (const float*)d_in[8];
    const float* gcaS = (const float*)d_in[9];
    const float* gcaD = (const float*)d_in[10];
    const float* gcB  = (const float*)d_in[11];
    const float* sgWn = (const float*)d_in[12];
    const float* sgWr = (const float*)d_in[13];
    const float* sgB  = (const float*)d_in[14];
    float* out = (float*)d_out;

    // fp16 prep
    k_prepx<<<(N_NODES * DIM / 2) / 256, 256>>>(x);
    k_prepw<<<dim3(64, 4), 256>>>(gpW, gcW, sgWn, sgWr);
    // CSR build: count -> atomic segment alloc -> fill
    k_count<<<dim3(N_EDGES / 256, 3), 256>>>(eip + N_EDGES, eic + N_EDGES, eir + N_EDGES);
    k_alloc<<<dim3(196, 3), 256>>>();
    k_fill<<<dim3(N_EDGES / 256, 3), 256>>>(eip, eip + N_EDGES,
                                            eic, eic + N_EDGES,
                                            eir, eir + N_EDGES);
    // tensor-core feature GEMMs + alpha scalars (launch #6 — ncu slot)
    k_feat<<<782, 256>>>(gpaS, gpaD, gcaS, gcaD);
    // per-dst aggregation (2 GATs + SAGE mean)
    k_agg<<<dim3(N_NODES / 8, 3), 256>>>();
    // tensor-core SAGE GEMMs + combine
    k_final<<<782, 128>>>(gpB, gcB, sgB, out);
}